// round 10
// baseline (speedup 1.0000x reference)
#include <cuda_runtime.h>
#include <stdint.h>

#define NMAX 50000
#define DD 128
#define NPW 8      // nodes per warp in proj-dot
#define TILE 1024  // edges per block in staged hop sweeps
#define TPB 256

// Scratch (no device allocs allowed)
__device__ int   g_mode;        // 1 = indices are int64, 0 = int32
__device__ float g_deg[NMAX];
__device__ float g_y[NMAX];     // x . W
__device__ float g_p[NMAX];
__device__ float g_q[NMAX];     // p * y   (hop-1 message value)
__device__ float g_r[NMAX];     // p * t   (hop-2 message value)
__device__ float g_acc1[NMAX];  // sum of q[src] per dst
__device__ float g_acc2[NMAX];  // sum of r[src] per dst

__device__ __forceinline__ void cp16(void* s, const void* g) {
    uint32_t sa = (uint32_t)__cvta_generic_to_shared(s);
    asm volatile("cp.async.cg.shared.global [%0], [%1], 16;" :: "r"(sa), "l"(g));
}

// ---------------------------------------------------------------------------
// K1: detect dtype (warp 0 of block 0) + deg[i]=1 + zero accumulators
__global__ void k_init(const long long* __restrict__ edge, int n) {
    if (blockIdx.x == 0 && threadIdx.x < 32) {
        long long v = edge[threadIdx.x];
        unsigned ok = __ballot_sync(0xffffffffu, v >= 0 && v < (long long)n);
        if (threadIdx.x == 0) g_mode = (ok == 0xffffffffu) ? 1 : 0;
    }
    int i = blockIdx.x * blockDim.x + threadIdx.x;
    if (i < n) {
        g_deg[i]  = 1.0f;
        g_acc1[i] = 0.0f;
        g_acc2[i] = 0.0f;
    }
}

// ---------------------------------------------------------------------------
// K2 (fused, block-specialized):
//   blocks [0, edgeBlocks)   : deg[dst] += 1, one edge per thread
//   blocks [edgeBlocks, ...) : y[node] = x[node] . W   (warp handles NPW nodes)
__global__ void k_deg_dot(const float* __restrict__ x, const float* __restrict__ W,
                          const long long* __restrict__ edge,
                          int e_cnt, int n, int edgeBlocks) {
    if (blockIdx.x < edgeBlocks) {
        int e = blockIdx.x * blockDim.x + threadIdx.x;
        if (e < e_cnt) {
            int dst = g_mode ? (int)edge[e_cnt + e] : ((const int*)edge)[e_cnt + e];
            if ((unsigned)dst < (unsigned)n)
                atomicAdd(&g_deg[dst], 1.0f);
        }
    } else {
        int bid = blockIdx.x - edgeBlocks;
        int warp = (bid * blockDim.x + threadIdx.x) >> 5;
        int lane = threadIdx.x & 31;
        int base = warp * NPW;
        if (base >= n) return;

        float4 w = __ldg(&((const float4*)W)[lane]);

        float4 a[NPW];
        #pragma unroll
        for (int k = 0; k < NPW; k++) {
            int node = base + k;
            if (node < n)
                a[k] = ((const float4*)(x + (size_t)node * DD))[lane];
            else
                a[k] = make_float4(0.f, 0.f, 0.f, 0.f);
        }

        float s[NPW];
        #pragma unroll
        for (int k = 0; k < NPW; k++)
            s[k] = a[k].x * w.x + a[k].y * w.y + a[k].z * w.z + a[k].w * w.w;

        #pragma unroll
        for (int off = 16; off > 0; off >>= 1) {
            #pragma unroll
            for (int k = 0; k < NPW; k++)
                s[k] += __shfl_down_sync(0xffffffffu, s[k], off);
        }

        if (lane == 0) {
            #pragma unroll
            for (int k = 0; k < NPW; k++) {
                int node = base + k;
                if (node < n) g_y[node] = s[k];
            }
        }
    }
}

// ---------------------------------------------------------------------------
// K3: p = rsqrt(deg), q = p*y
__global__ void k_pq(int n) {
    int i = blockIdx.x * blockDim.x + threadIdx.x;
    if (i < n) {
        float p = rsqrtf(g_deg[i]);
        g_p[i] = p;
        g_q[i] = p * g_y[i];
    }
}

// ---------------------------------------------------------------------------
// Staged hop sweep: acc[dst] += val[src].
// Full tiles: cp.async the TILE-edge index slab into smem (async pipe, off the
// LDG scoreboard), then each thread does only random gather + atomic.
// Tail tile (last block, partial): direct scalar loads.
__device__ __forceinline__ void hop_sweep(const long long* __restrict__ edge,
                                          int e_cnt, int n,
                                          const float* __restrict__ val,
                                          float* __restrict__ acc,
                                          int fullTiles) {
    __shared__ __align__(16) char s_raw[2 * TILE * 8];   // worst case: int64
    int tid = threadIdx.x;
    int tile0 = blockIdx.x * TILE;
    int mode = g_mode;

    if ((int)blockIdx.x < fullTiles) {
        if (mode) {
            const char* gs = (const char*)(edge + tile0);
            const char* gd = (const char*)(edge + e_cnt + tile0);
            char* ss = s_raw;
            char* sd = s_raw + TILE * 8;
            #pragma unroll
            for (int i = 0; i < TILE * 8; i += TPB * 16) {
                cp16(ss + i + tid * 16, gs + i + tid * 16);
                cp16(sd + i + tid * 16, gd + i + tid * 16);
            }
        } else {
            const int* e32 = (const int*)edge;
            const char* gs = (const char*)(e32 + tile0);
            const char* gd = (const char*)(e32 + e_cnt + tile0);
            char* ss = s_raw;
            char* sd = s_raw + TILE * 4;
            #pragma unroll
            for (int i = 0; i < TILE * 4; i += TPB * 16) {
                cp16(ss + i + tid * 16, gs + i + tid * 16);
                cp16(sd + i + tid * 16, gd + i + tid * 16);
            }
        }
        asm volatile("cp.async.commit_group;");
        asm volatile("cp.async.wait_group 0;");
        __syncthreads();

        #pragma unroll
        for (int k = 0; k < TILE / TPB; k++) {
            int li = tid + k * TPB;
            int src, dst;
            if (mode) {
                src = (int)((const long long*)s_raw)[li];
                dst = (int)((const long long*)(s_raw + TILE * 8))[li];
            } else {
                src = ((const int*)s_raw)[li];
                dst = ((const int*)(s_raw + TILE * 4))[li];
            }
            if ((unsigned)src < (unsigned)n && (unsigned)dst < (unsigned)n)
                atomicAdd(&acc[dst], val[src]);
        }
    } else {
        // partial tail tile: direct loads
        #pragma unroll
        for (int k = 0; k < TILE / TPB; k++) {
            int e = tile0 + tid + k * TPB;
            if (e < e_cnt) {
                int src = mode ? (int)edge[e] : ((const int*)edge)[e];
                int dst = mode ? (int)edge[e_cnt + e] : ((const int*)edge)[e_cnt + e];
                if ((unsigned)src < (unsigned)n && (unsigned)dst < (unsigned)n)
                    atomicAdd(&acc[dst], val[src]);
            }
        }
    }
}

__global__ void k_hop1(const long long* __restrict__ edge, int e_cnt, int n, int fullTiles) {
    hop_sweep(edge, e_cnt, n, g_q, g_acc1, fullTiles);
}

__global__ void k_hop2(const long long* __restrict__ edge, int e_cnt, int n, int fullTiles) {
    hop_sweep(edge, e_cnt, n, g_r, g_acc2, fullTiles);
}

// ---------------------------------------------------------------------------
// K5: r = p*p*(q + acc1)
__global__ void k_mid(int n) {
    int i = blockIdx.x * blockDim.x + threadIdx.x;
    if (i < n) {
        float p = g_p[i];
        g_r[i] = p * p * (g_q[i] + g_acc1[i]);
    }
}

// K7: out[i] = p*(r + acc2) + b
__global__ void k_final(float* __restrict__ out, const float* __restrict__ b, int n) {
    int i = blockIdx.x * blockDim.x + threadIdx.x;
    if (i < n) {
        out[i] = g_p[i] * (g_r[i] + g_acc2[i]) + b[0];
    }
}

extern "C" void kernel_launch(void* const* d_in, const int* in_sizes, int n_in,
                              void* d_out, int out_size) {
    const float*     x    = (const float*)d_in[0];       // [N, 128]
    const long long* edge = (const long long*)d_in[1];   // [2, E] indices
    const float*     W    = (const float*)d_in[2];       // [1, 128]
    const float*     b    = (const float*)d_in[3];       // [1]
    float*           out  = (float*)d_out;               // [N]

    int n = in_sizes[0] / DD;
    if (n > NMAX) n = NMAX;
    const int e_cnt = in_sizes[1] / 2;

    const int nBlkN = (n + TPB - 1) / TPB;
    const int nBlkE = (e_cnt + TPB - 1) / TPB;            // one edge / thread (deg)
    const int nWarps = (n + NPW - 1) / NPW;
    const int nBlkW = (nWarps * 32 + TPB - 1) / TPB;

    const int fullTiles = e_cnt / TILE;
    const int nBlkH = fullTiles + ((e_cnt % TILE) ? 1 : 0);

    k_init<<<nBlkN, TPB>>>(edge, n);
    k_deg_dot<<<nBlkE + nBlkW, TPB>>>(x, W, edge, e_cnt, n, nBlkE);
    k_pq<<<nBlkN, TPB>>>(n);
    k_hop1<<<nBlkH, TPB>>>(edge, e_cnt, n, fullTiles);
    k_mid<<<nBlkN, TPB>>>(n);
    k_hop2<<<nBlkH, TPB>>>(edge, e_cnt, n, fullTiles);
    k_final<<<nBlkN, TPB>>>(out, b, n);
}

// round 11
// speedup vs baseline: 1.0467x; 1.0467x over previous
#include <cuda_runtime.h>
#include <stdint.h>

#define NMAX 50000
#define DD 128
#define NPW 8      // nodes per warp in proj-dot
#define TPB 256
#define HTPB 1024  // threads per block in staged hop sweeps
#define HGRID 148  // one block per SM

// Scratch (no device allocs allowed)
__device__ int   g_mode;        // 1 = indices are int64, 0 = int32
__device__ float g_deg[NMAX];
__device__ float g_y[NMAX];     // x . W
__device__ float g_p[NMAX];
__device__ float g_q[NMAX];     // p * y   (hop-1 message value)
__device__ float g_r[NMAX];     // p * t   (hop-2 message value)
__device__ float g_acc1[NMAX];  // sum of q[src] per dst
__device__ float g_acc2[NMAX];  // sum of r[src] per dst

// ---------------------------------------------------------------------------
// K1: detect dtype (warp 0 of block 0) + deg[i]=1 + zero accumulators
__global__ void k_init(const long long* __restrict__ edge, int n) {
    if (blockIdx.x == 0 && threadIdx.x < 32) {
        long long v = edge[threadIdx.x];
        unsigned ok = __ballot_sync(0xffffffffu, v >= 0 && v < (long long)n);
        if (threadIdx.x == 0) g_mode = (ok == 0xffffffffu) ? 1 : 0;
    }
    int i = blockIdx.x * blockDim.x + threadIdx.x;
    if (i < n) {
        g_deg[i]  = 1.0f;
        g_acc1[i] = 0.0f;
        g_acc2[i] = 0.0f;
    }
}

// ---------------------------------------------------------------------------
// K2 (fused, block-specialized):
//   blocks [0, edgeBlocks)   : deg[dst] += 1, one edge per thread
//   blocks [edgeBlocks, ...) : y[node] = x[node] . W   (warp handles NPW nodes)
__global__ void k_deg_dot(const float* __restrict__ x, const float* __restrict__ W,
                          const long long* __restrict__ edge,
                          int e_cnt, int n, int edgeBlocks) {
    if (blockIdx.x < edgeBlocks) {
        int e = blockIdx.x * blockDim.x + threadIdx.x;
        if (e < e_cnt) {
            int dst = g_mode ? (int)edge[e_cnt + e] : ((const int*)edge)[e_cnt + e];
            if ((unsigned)dst < (unsigned)n)
                atomicAdd(&g_deg[dst], 1.0f);
        }
    } else {
        int bid = blockIdx.x - edgeBlocks;
        int warp = (bid * blockDim.x + threadIdx.x) >> 5;
        int lane = threadIdx.x & 31;
        int base = warp * NPW;
        if (base >= n) return;

        float4 w = __ldg(&((const float4*)W)[lane]);

        float4 a[NPW];
        #pragma unroll
        for (int k = 0; k < NPW; k++) {
            int node = base + k;
            if (node < n)
                a[k] = ((const float4*)(x + (size_t)node * DD))[lane];
            else
                a[k] = make_float4(0.f, 0.f, 0.f, 0.f);
        }

        float s[NPW];
        #pragma unroll
        for (int k = 0; k < NPW; k++)
            s[k] = a[k].x * w.x + a[k].y * w.y + a[k].z * w.z + a[k].w * w.w;

        #pragma unroll
        for (int off = 16; off > 0; off >>= 1) {
            #pragma unroll
            for (int k = 0; k < NPW; k++)
                s[k] += __shfl_down_sync(0xffffffffu, s[k], off);
        }

        if (lane == 0) {
            #pragma unroll
            for (int k = 0; k < NPW; k++) {
                int node = base + k;
                if (node < n) g_y[node] = s[k];
            }
        }
    }
}

// ---------------------------------------------------------------------------
// K3: p = rsqrt(deg), q = p*y
__global__ void k_pq(int n) {
    int i = blockIdx.x * blockDim.x + threadIdx.x;
    if (i < n) {
        float p = rsqrtf(g_deg[i]);
        g_p[i] = p;
        g_q[i] = p * g_y[i];
    }
}

// ---------------------------------------------------------------------------
// Staged hop: stage the ENTIRE value array (n floats, <=200KB) into shared
// memory, then sweep this block's edge slice: random gather becomes LDS
// (cheap bank phases instead of L1tex line-divergence wavefronts); only the
// scatter atomic stays global.
__device__ __forceinline__ void hop_sweep_smem(const long long* __restrict__ edge,
                                               int e_cnt, int n,
                                               const float* __restrict__ val,
                                               float* __restrict__ acc) {
    extern __shared__ float s_val[];
    int tid = threadIdx.x;

    // stage val -> smem (coalesced float4)
    int nv4 = n >> 2;
    const float4* v4 = (const float4*)val;
    float4* s4 = (float4*)s_val;
    for (int i = tid; i < nv4; i += HTPB) s4[i] = v4[i];
    for (int i = (nv4 << 2) + tid; i < n; i += HTPB) s_val[i] = val[i];
    __syncthreads();

    // this block's contiguous edge slice
    int chunk = (e_cnt + HGRID - 1) / HGRID;
    int start = blockIdx.x * chunk;
    int end   = min(start + chunk, e_cnt);
    int mode  = g_mode;

    const int* e32 = (const int*)edge;

    // 4-way unrolled: 8 independent coalesced index loads in flight
    int e = start + tid;
    for (; e + 3 * HTPB < end; e += 4 * HTPB) {
        int s0, s1, s2, s3, d0, d1, d2, d3;
        if (mode) {
            s0 = (int)edge[e];             d0 = (int)edge[e_cnt + e];
            s1 = (int)edge[e + HTPB];      d1 = (int)edge[e_cnt + e + HTPB];
            s2 = (int)edge[e + 2 * HTPB];  d2 = (int)edge[e_cnt + e + 2 * HTPB];
            s3 = (int)edge[e + 3 * HTPB];  d3 = (int)edge[e_cnt + e + 3 * HTPB];
        } else {
            s0 = e32[e];             d0 = e32[e_cnt + e];
            s1 = e32[e + HTPB];      d1 = e32[e_cnt + e + HTPB];
            s2 = e32[e + 2 * HTPB];  d2 = e32[e_cnt + e + 2 * HTPB];
            s3 = e32[e + 3 * HTPB];  d3 = e32[e_cnt + e + 3 * HTPB];
        }
        bool ok0 = (unsigned)s0 < (unsigned)n && (unsigned)d0 < (unsigned)n;
        bool ok1 = (unsigned)s1 < (unsigned)n && (unsigned)d1 < (unsigned)n;
        bool ok2 = (unsigned)s2 < (unsigned)n && (unsigned)d2 < (unsigned)n;
        bool ok3 = (unsigned)s3 < (unsigned)n && (unsigned)d3 < (unsigned)n;
        float v0 = ok0 ? s_val[s0] : 0.f;
        float v1 = ok1 ? s_val[s1] : 0.f;
        float v2 = ok2 ? s_val[s2] : 0.f;
        float v3 = ok3 ? s_val[s3] : 0.f;
        if (ok0) atomicAdd(&acc[d0], v0);
        if (ok1) atomicAdd(&acc[d1], v1);
        if (ok2) atomicAdd(&acc[d2], v2);
        if (ok3) atomicAdd(&acc[d3], v3);
    }
    for (; e < end; e += HTPB) {
        int src = mode ? (int)edge[e] : e32[e];
        int dst = mode ? (int)edge[e_cnt + e] : e32[e_cnt + e];
        if ((unsigned)src < (unsigned)n && (unsigned)dst < (unsigned)n)
            atomicAdd(&acc[dst], s_val[src]);
    }
}

__global__ void k_hop1(const long long* __restrict__ edge, int e_cnt, int n) {
    hop_sweep_smem(edge, e_cnt, n, g_q, g_acc1);
}

__global__ void k_hop2(const long long* __restrict__ edge, int e_cnt, int n) {
    hop_sweep_smem(edge, e_cnt, n, g_r, g_acc2);
}

// ---------------------------------------------------------------------------
// K5: r = p*p*(q + acc1)
__global__ void k_mid(int n) {
    int i = blockIdx.x * blockDim.x + threadIdx.x;
    if (i < n) {
        float p = g_p[i];
        g_r[i] = p * p * (g_q[i] + g_acc1[i]);
    }
}

// K7: out[i] = p*(r + acc2) + b
__global__ void k_final(float* __restrict__ out, const float* __restrict__ b, int n) {
    int i = blockIdx.x * blockDim.x + threadIdx.x;
    if (i < n) {
        out[i] = g_p[i] * (g_r[i] + g_acc2[i]) + b[0];
    }
}

extern "C" void kernel_launch(void* const* d_in, const int* in_sizes, int n_in,
                              void* d_out, int out_size) {
    const float*     x    = (const float*)d_in[0];       // [N, 128]
    const long long* edge = (const long long*)d_in[1];   // [2, E] indices
    const float*     W    = (const float*)d_in[2];       // [1, 128]
    const float*     b    = (const float*)d_in[3];       // [1]
    float*           out  = (float*)d_out;               // [N]

    int n = in_sizes[0] / DD;
    if (n > NMAX) n = NMAX;
    const int e_cnt = in_sizes[1] / 2;

    const int nBlkN = (n + TPB - 1) / TPB;
    const int nBlkE = (e_cnt + TPB - 1) / TPB;
    const int nWarps = (n + NPW - 1) / NPW;
    const int nBlkW = (nWarps * 32 + TPB - 1) / TPB;

    const int smemBytes = ((n * 4 + 127) / 128) * 128;   // staged value array

    cudaFuncSetAttribute(k_hop1, cudaFuncAttributeMaxDynamicSharedMemorySize, smemBytes);
    cudaFuncSetAttribute(k_hop2, cudaFuncAttributeMaxDynamicSharedMemorySize, smemBytes);

    k_init<<<nBlkN, TPB>>>(edge, n);
    k_deg_dot<<<nBlkE + nBlkW, TPB>>>(x, W, edge, e_cnt, n, nBlkE);
    k_pq<<<nBlkN, TPB>>>(n);
    k_hop1<<<HGRID, HTPB, smemBytes>>>(edge, e_cnt, n);
    k_mid<<<nBlkN, TPB>>>(n);
    k_hop2<<<HGRID, HTPB, smemBytes>>>(edge, e_cnt, n);
    k_final<<<nBlkN, TPB>>>(out, b, n);
}